// round 16
// baseline (speedup 1.0000x reference)
#include <cuda_runtime.h>
#include <math.h>
#include <stdint.h>

// Problem constants
#define Bb   2
#define Nn   1024
#define Cc   1024
#define Hh   16
#define Dd   64
#define BLKc 8
#define NBc  128
#define TOPKc 7
#define BHc  (Bb*Hh)          // 32
#define NCHUNK 16
#define CHLEN (Nn/NCHUNK)     // 64
#define K2c  (Cc/2)           // 512 bf16-pair columns

// ---------------- scratch (device globals; no allocation) ----------------
__device__ __align__(16) float g_q   [BHc*Nn*Dd];
__device__ __align__(16) float g_k   [BHc*Nn*Dd];
__device__ __align__(16) float g_v   [BHc*Nn*Dd];
__device__ __align__(16) float g_pq  [BHc*Nn*Dd];
__device__ __align__(16) float g_pk  [BHc*Nn*Dd];
__device__ __align__(16) float g_kcmp[BHc*NBc*Dd];
__device__               int   g_topk[BHc*Nn*TOPKc];
__device__ __align__(16) float g_kvp [NCHUNK*BHc*Dd*Dd];
__device__ __align__(16) float g_zp  [NCHUNK*BHc*Dd];
__device__ __align__(16) float g_kv  [BHc*Dd*Dd];
__device__ __align__(16) float g_z   [BHc*Dd];
// bf16 hi/lo packed pair operands
__device__ __align__(16) uint32_t g_xh [Bb*Nn*K2c];
__device__ __align__(16) uint32_t g_xl [Bb*Nn*K2c];
__device__ __align__(16) uint32_t g_ah [Bb*Nn*K2c];   // attn output planes
__device__ __align__(16) uint32_t g_al [Bb*Nn*K2c];
__device__ __align__(16) uint32_t g_wvh[K2c*Cc];
__device__ __align__(16) uint32_t g_wvl[K2c*Cc];
__device__ __align__(16) uint32_t g_wph[K2c*Cc];
__device__ __align__(16) uint32_t g_wpl[K2c*Cc];

// ---------------- helpers -------------------------------------------------
__device__ __forceinline__ uint32_t f2tf32(float x) {
    uint32_t r;
    asm("cvt.rna.tf32.f32 %0, %1;" : "=r"(r) : "f"(x));
    return r;
}

__device__ __forceinline__ void bf16_split2(float x0, float x1,
                                            uint32_t& ph, uint32_t& pl) {
    uint32_t h;
    asm("cvt.rn.bf16x2.f32 %0, %1, %2;" : "=r"(h) : "f"(x1), "f"(x0));
    float h0 = __uint_as_float(h << 16);
    float h1 = __uint_as_float(h & 0xffff0000u);
    float r0 = x0 - h0, r1 = x1 - h1;
    uint32_t l;
    asm("cvt.rn.bf16x2.f32 %0, %1, %2;" : "=r"(l) : "f"(r1), "f"(r0));
    ph = h; pl = l;
}

__device__ __forceinline__ void mma_tf32(float* d, const uint32_t* a, const uint32_t* b) {
    asm volatile(
        "mma.sync.aligned.m16n8k8.row.col.f32.tf32.tf32.f32 "
        "{%0,%1,%2,%3}, {%4,%5,%6,%7}, {%8,%9}, {%0,%1,%2,%3};"
        : "+f"(d[0]), "+f"(d[1]), "+f"(d[2]), "+f"(d[3])
        : "r"(a[0]), "r"(a[1]), "r"(a[2]), "r"(a[3]), "r"(b[0]), "r"(b[1]));
}

__device__ __forceinline__ void mma_bf16(float* d, const uint32_t* a, const uint32_t* b) {
    asm volatile(
        "mma.sync.aligned.m16n8k16.row.col.f32.bf16.bf16.f32 "
        "{%0,%1,%2,%3}, {%4,%5,%6,%7}, {%8,%9}, {%0,%1,%2,%3};"
        : "+f"(d[0]), "+f"(d[1]), "+f"(d[2]), "+f"(d[3])
        : "r"(a[0]), "r"(a[1]), "r"(a[2]), "r"(a[3]), "r"(b[0]), "r"(b[1]));
}

#define CP_ASYNC16(saddr, gptr) \
    asm volatile("cp.async.cg.shared.global [%0], [%1], 16;" :: "r"(saddr), "l"(gptr))
#define CP_COMMIT() asm volatile("cp.async.commit_group;")
#define CP_WAIT1()  asm volatile("cp.async.wait_group 1;")
#define CP_WAIT0()  asm volatile("cp.async.wait_group 0;")

// ---------------- split kernels -------------------------------------------
__global__ __launch_bounds__(256) void split_a_kernel(
    const float* __restrict__ in, uint32_t* __restrict__ oh,
    uint32_t* __restrict__ ol, int npairs)
{
    int i = blockIdx.x * 256 + threadIdx.x;
    if (i >= npairs) return;
    float2 v = reinterpret_cast<const float2*>(in)[i];
    uint32_t h, l;
    bf16_split2(v.x, v.y, h, l);
    oh[i] = h; ol[i] = l;
}

__global__ __launch_bounds__(256) void split_b_kernel(
    const float* __restrict__ in, uint32_t* __restrict__ oh,
    uint32_t* __restrict__ ol, int ldb)
{
    int i = blockIdx.x * 256 + threadIdx.x;
    int k2 = i >> 10, n = i & 1023;
    float x0 = in[(size_t)(2*k2)   * ldb + n];
    float x1 = in[(size_t)(2*k2+1) * ldb + n];
    uint32_t h, l;
    bf16_split2(x0, x1, h, l);
    oh[i] = h; ol[i] = l;
}

// =============== GEMM tile device functions (cp.async staging) ============
#define GBM 128
#define GBN 64
#define GBK 16
#define ASTR2 20
#define ATILE2 (GBM*ASTR2)   // 2560 floats per buf
#define BSTR 72
#define BTILE (GBK*BSTR)     // 1152
#define HASTR2 12
#define HATILE2 (GBM*HASTR2) // 1536 u32 per buf
#define HBSTR 72
#define HBTILE (8*HBSTR)     // 576
// epilogue staging tile: 128 x 66 floats = 8448 (also >= mainloop needs)
#define SMEM_U32_TOTAL 8448
#define EPSTR 66
#define NTILE_TOTAL 768
#define PERSIST_GRID 444       // 148 SMs x 3 CTAs

// ---- 3xTF32 q/k tile: R13 double-buffer mainloop; epilogue = LN + phi ----
__device__ __forceinline__ void gemm_qk_tile(
    const float* __restrict__ A, const float* __restrict__ B,
    const float* __restrict__ bias,
    const float* __restrict__ qw, const float* __restrict__ qb,
    const float* __restrict__ kw, const float* __restrict__ kb,
    int K, int ldb, int bm, int bn, uint32_t* smraw)
{
    float* As = reinterpret_cast<float*>(smraw);
    float* Bs = reinterpret_cast<float*>(smraw + 2*ATILE2);
    const int tid  = threadIdx.x;
    const int lane = tid & 31;
    const int warp = tid >> 5;
    const int warpM = warp & 3;
    const int warpN = warp >> 2;
    const int g  = lane >> 2;
    const int tq = lane & 3;

    const int aRow = tid >> 1;
    const int aQf  = (tid & 1) * 8;
    const int bRow = tid >> 4;
    const int bQf  = (tid & 15) * 4;

    const uint32_t as_u = (uint32_t)__cvta_generic_to_shared(As);
    const uint32_t bs_u = (uint32_t)__cvta_generic_to_shared(Bs);

    float acc[2][4][4];
#pragma unroll
    for (int mf = 0; mf < 2; mf++)
#pragma unroll
        for (int nf = 0; nf < 4; nf++)
#pragma unroll
            for (int r = 0; r < 4; r++) acc[mf][nf][r] = 0.f;

    const int nIter = K / GBK;

    {
        const float* ga = A + (size_t)(bm + aRow) * K + aQf;
        uint32_t sa = as_u + (aRow*ASTR2 + aQf) * 4;
        CP_ASYNC16(sa, ga);
        CP_ASYNC16(sa + 16, ga + 4);
        const float* gb = B + (size_t)bRow * ldb + bn + bQf;
        uint32_t sb = bs_u + (bRow*BSTR + bQf) * 4;
        CP_ASYNC16(sb, gb);
        CP_COMMIT();
    }

    for (int it = 0; it < nIter; it++) {
        const int buf = it & 1;
        const bool more = (it + 1 < nIter);
        if (more) {
            int k0 = (it + 1) * GBK;
            int nbuf = buf ^ 1;
            const float* ga = A + (size_t)(bm + aRow) * K + k0 + aQf;
            uint32_t sa = as_u + (nbuf*ATILE2 + aRow*ASTR2 + aQf) * 4;
            CP_ASYNC16(sa, ga);
            CP_ASYNC16(sa + 16, ga + 4);
            const float* gb = B + (size_t)(k0 + bRow) * ldb + bn + bQf;
            uint32_t sb = bs_u + (nbuf*BTILE + bRow*BSTR + bQf) * 4;
            CP_ASYNC16(sb, gb);
            CP_COMMIT();
            CP_WAIT1();
        } else {
            CP_WAIT0();
        }
        __syncthreads();

        const float* as = As + buf*ATILE2;
        const float* bs = Bs + buf*BTILE;
#pragma unroll
        for (int ks = 0; ks < 2; ks++) {
            const int kb = ks * 8;
            uint32_t ahi[2][4], alo[2][4];
#pragma unroll
            for (int mf = 0; mf < 2; mf++) {
                const int m = warpM * 32 + mf * 16 + g;
                float v0 = as[m*ASTR2 + kb + tq];
                float v1 = as[(m+8)*ASTR2 + kb + tq];
                float v2 = as[m*ASTR2 + kb + tq + 4];
                float v3 = as[(m+8)*ASTR2 + kb + tq + 4];
                ahi[mf][0] = f2tf32(v0); alo[mf][0] = f2tf32(v0 - __uint_as_float(ahi[mf][0]));
                ahi[mf][1] = f2tf32(v1); alo[mf][1] = f2tf32(v1 - __uint_as_float(ahi[mf][1]));
                ahi[mf][2] = f2tf32(v2); alo[mf][2] = f2tf32(v2 - __uint_as_float(ahi[mf][2]));
                ahi[mf][3] = f2tf32(v3); alo[mf][3] = f2tf32(v3 - __uint_as_float(ahi[mf][3]));
            }
            uint32_t bhi[4][2], blo[4][2];
#pragma unroll
            for (int nf = 0; nf < 4; nf++) {
                const int n = warpN * 32 + nf * 8 + g;
                float v0 = bs[(kb + tq) * BSTR + n];
                float v1 = bs[(kb + tq + 4) * BSTR + n];
                bhi[nf][0] = f2tf32(v0); blo[nf][0] = f2tf32(v0 - __uint_as_float(bhi[nf][0]));
                bhi[nf][1] = f2tf32(v1); blo[nf][1] = f2tf32(v1 - __uint_as_float(bhi[nf][1]));
            }
#pragma unroll
            for (int mf = 0; mf < 2; mf++)
#pragma unroll
                for (int nf = 0; nf < 4; nf++) mma_tf32(acc[mf][nf], ahi[mf], bhi[nf]);
#pragma unroll
            for (int mf = 0; mf < 2; mf++)
#pragma unroll
                for (int nf = 0; nf < 4; nf++) mma_tf32(acc[mf][nf], alo[mf], bhi[nf]);
#pragma unroll
            for (int mf = 0; mf < 2; mf++)
#pragma unroll
                for (int nf = 0; nf < 4; nf++) mma_tf32(acc[mf][nf], ahi[mf], blo[nf]);
        }
        __syncthreads();
    }

    // ---- epilogue: stage acc+bias into smem, then LN + phi per row ----
    float* so = reinterpret_cast<float*>(smraw);   // 128 x EPSTR
#pragma unroll
    for (int mf = 0; mf < 2; mf++) {
#pragma unroll
        for (int nf = 0; nf < 4; nf++) {
            int lr = warpM * 32 + mf * 16 + g;
            int lc = warpN * 32 + nf * 8 + tq * 2;
            float2 bv = *reinterpret_cast<const float2*>(bias + bn + lc);
            so[lr*EPSTR + lc]       = acc[mf][nf][0] + bv.x;
            so[lr*EPSTR + lc + 1]   = acc[mf][nf][1] + bv.y;
            so[(lr+8)*EPSTR + lc]   = acc[mf][nf][2] + bv.x;
            so[(lr+8)*EPSTR + lc+1] = acc[mf][nf][3] + bv.y;
        }
    }
    __syncthreads();

    const int slot = bn >> 6;              // 0..31
    const bool isq = slot < 16;
    const int h = isq ? slot : slot - 16;
    const float* lw = isq ? qw : kw;
    const float* lb = isq ? qb : kb;
    float* gv = isq ? g_q : g_k;
    float* gp = isq ? g_pq : g_pk;
    const int d0 = lane, d1 = lane + 32;
    const float wd0 = lw[d0], wd1 = lw[d1];
    const float bd0 = lb[d0], bd1 = lb[d1];

    for (int rr = 0; rr < 16; rr++) {
        int row = warp * 16 + rr;
        int mtok = bm + row;
        int btok = mtok >> 10, n = mtok & 1023;
        size_t obase = ((size_t)(btok*Hh + h) * Nn + n) * Dd;
        float v0 = so[row*EPSTR + d0];
        float v1 = so[row*EPSTR + d1];
        float s = v0 + v1;
#pragma unroll
        for (int o = 16; o; o >>= 1) s += __shfl_xor_sync(~0u, s, o);
        float m = s * (1.f/64.f);
        float a0 = v0 - m, a1 = v1 - m;
        float vs = a0*a0 + a1*a1;
#pragma unroll
        for (int o = 16; o; o >>= 1) vs += __shfl_xor_sync(~0u, vs, o);
        float r = rsqrtf(vs * (1.f/64.f) + 1e-6f);
        float y0 = a0*r*wd0 + bd0;
        float y1 = a1*r*wd1 + bd1;
        gv[obase + d0] = y0; gv[obase + d1] = y1;
        float mx = fmaxf(y0, y1);
#pragma unroll
        for (int o = 16; o; o >>= 1) mx = fmaxf(mx, __shfl_xor_sync(~0u, mx, o));
        float e0 = __expf(y0 - mx), e1 = __expf(y1 - mx);
        float se = e0 + e1;
#pragma unroll
        for (int o = 16; o; o >>= 1) se += __shfl_xor_sync(~0u, se, o);
        float inv = 1.f / se;
        gp[obase + d0] = e0*inv; gp[obase + d1] = e1*inv;
    }
}

// ---- pre-split 3xbf16 v tile: R13 mainloop; epilogue scatters g_v --------
__device__ __forceinline__ void gemm_v_tile(
    const uint32_t* __restrict__ Ah, const uint32_t* __restrict__ Al,
    const uint32_t* __restrict__ Bh, const uint32_t* __restrict__ Bl,
    const float* __restrict__ bias,
    int K2, int N, int bm, int bn, uint32_t* smraw)
{
    uint32_t* Ahs = smraw;
    uint32_t* Als = smraw + 2*HATILE2;
    uint32_t* Bhs = smraw + 4*HATILE2;
    uint32_t* Bls = smraw + 4*HATILE2 + 2*HBTILE;
    const int tid  = threadIdx.x;
    const int lane = tid & 31;
    const int warp = tid >> 5;
    const int warpM = warp & 3;
    const int warpN = warp >> 2;
    const int g  = lane >> 2;
    const int tq = lane & 3;

    const int aRow = tid >> 1;
    const int aQ   = (tid & 1) * 4;
    const int bSel = tid >> 7;
    const int bT   = tid & 127;
    const int bRow = bT >> 4;
    const int bQ   = (bT & 15) * 4;

    const uint32_t ah_u = (uint32_t)__cvta_generic_to_shared(Ahs);
    const uint32_t al_u = (uint32_t)__cvta_generic_to_shared(Als);
    const uint32_t bh_u = (uint32_t)__cvta_generic_to_shared(Bhs);
    const uint32_t bl_u = (uint32_t)__cvta_generic_to_shared(Bls);

    float acc[2][4][4];
#pragma unroll
    for (int mf = 0; mf < 2; mf++)
#pragma unroll
        for (int nf = 0; nf < 4; nf++)
#pragma unroll
            for (int r = 0; r < 4; r++) acc[mf][nf][r] = 0.f;

    const int nIter = K2 / 8;

    {
        const uint32_t* gah = Ah + (size_t)(bm + aRow) * K2 + aQ;
        const uint32_t* gal = Al + (size_t)(bm + aRow) * K2 + aQ;
        uint32_t sa = (aRow*HASTR2 + aQ) * 4;
        CP_ASYNC16(ah_u + sa, gah);
        CP_ASYNC16(al_u + sa, gal);
        const uint32_t* gb = (bSel ? Bl : Bh) + (size_t)bRow * N + bn + bQ;
        uint32_t sb = (bSel ? bl_u : bh_u) + (bRow*HBSTR + bQ) * 4;
        CP_ASYNC16(sb, gb);
        CP_COMMIT();
    }

    for (int it = 0; it < nIter; it++) {
        const int buf = it & 1;
        const bool more = (it + 1 < nIter);
        if (more) {
            int k2o = (it + 1) * 8;
            int nbuf = buf ^ 1;
            const uint32_t* gah = Ah + (size_t)(bm + aRow) * K2 + k2o + aQ;
            const uint32_t* gal = Al + (size_t)(bm + aRow) * K2 + k2o + aQ;
            uint32_t sa = (nbuf*HATILE2 + aRow*HASTR2 + aQ) * 4;
            CP_ASYNC16(ah_u + sa, gah);
            CP_ASYNC16(al_u + sa, gal);
            const uint32_t* gb = (bSel ? Bl : Bh) + (size_t)(k2o + bRow) * N + bn + bQ;
            uint32_t sb = (bSel ? bl_u : bh_u) + (nbuf*HBTILE + bRow*HBSTR + bQ) * 4;
            CP_ASYNC16(sb, gb);
            CP_COMMIT();
            CP_WAIT1();
        } else {
            CP_WAIT0();
        }
        __syncthreads();

        const uint32_t* ahs = Ahs + buf*HATILE2;
        const uint32_t* als = Als + buf*HATILE2;
        const uint32_t* bhs = Bhs + buf*HBTILE;
        const uint32_t* bls = Bls + buf*HBTILE;

        uint32_t ah[2][4], al[2][4];
#pragma unroll
        for (int mf = 0; mf < 2; mf++) {
            const int m = warpM * 32 + mf * 16 + g;
            ah[mf][0] = ahs[m*HASTR2 + tq];
            ah[mf][1] = ahs[(m+8)*HASTR2 + tq];
            ah[mf][2] = ahs[m*HASTR2 + tq + 4];
            ah[mf][3] = ahs[(m+8)*HASTR2 + tq + 4];
            al[mf][0] = als[m*HASTR2 + tq];
            al[mf][1] = als[(m+8)*HASTR2 + tq];
            al[mf][2] = als[m*HASTR2 + tq + 4];
            al[mf][3] = als[(m+8)*HASTR2 + tq + 4];
        }
        uint32_t bh[4][2], bl[4][2];
#pragma unroll
        for (int nf = 0; nf < 4; nf++) {
            const int n = warpN * 32 + nf * 8 + g;
            bh[nf][0] = bhs[tq*HBSTR + n];
            bh[nf][1] = bhs[(tq+4)*HBSTR + n];
            bl[nf][0] = bls[tq*HBSTR + n];
            bl[nf][1] = bls[(tq+4)*HBSTR + n];
        }
#pragma unroll
        for (int mf = 0; mf < 2; mf++)
#pragma unroll
            for (int nf = 0; nf < 4; nf++) mma_bf16(acc[mf][nf], ah[mf], bh[nf]);
#pragma unroll
        for (int mf = 0; mf < 2; mf++)
#pragma unroll
            for (int nf = 0; nf < 4; nf++) mma_bf16(acc[mf][nf], al[mf], bh[nf]);
#pragma unroll
        for (int mf = 0; mf < 2; mf++)
#pragma unroll
            for (int nf = 0; nf < 4; nf++) mma_bf16(acc[mf][nf], ah[mf], bl[nf]);

        __syncthreads();
    }

    // epilogue: scatter into g_v (B,H,N,D); whole tile is one head (bn/64)
    const int h = bn >> 6;
#pragma unroll
    for (int mf = 0; mf < 2; mf++) {
#pragma unroll
        for (int nf = 0; nf < 4; nf++) {
            const int r0 = bm + warpM * 32 + mf * 16 + g;
            const int c0 = bn + warpN * 32 + nf * 8 + tq * 2;
            const int d = c0 & 63;
            float2 bv = *reinterpret_cast<const float2*>(bias + c0);
            {
                int btok = r0 >> 10, n = r0 & 1023;
                size_t off = ((size_t)(btok*Hh + h) * Nn + n) * Dd + d;
                float2 o0 = make_float2(acc[mf][nf][0] + bv.x, acc[mf][nf][1] + bv.y);
                *reinterpret_cast<float2*>(g_v + off) = o0;
            }
            {
                int r1 = r0 + 8;
                int btok = r1 >> 10, n = r1 & 1023;
                size_t off = ((size_t)(btok*Hh + h) * Nn + n) * Dd + d;
                float2 o1 = make_float2(acc[mf][nf][2] + bv.x, acc[mf][nf][3] + bv.y);
                *reinterpret_cast<float2*>(g_v + off) = o1;
            }
        }
    }
}

// =============== persistent fused QKV kernel ==============================
// grid = 444 (148 SMs x 3 CTAs); each block loops over tiles bid, bid+444.
__global__ __launch_bounds__(256, 3) void qkv_mega_kernel(
    const float* __restrict__ x, const float* __restrict__ w_qkv,
    const float* __restrict__ b_qkv,
    const float* __restrict__ qw, const float* __restrict__ qb,
    const float* __restrict__ kw, const float* __restrict__ kb)
{
    __shared__ uint32_t sm[SMEM_U32_TOTAL];
    for (int t = blockIdx.x; t < NTILE_TOTAL; t += PERSIST_GRID) {
        if (t < 512) {
            int bn = (t & 31) * GBN;
            int bm = (t >> 5) * GBM;
            gemm_qk_tile(x, w_qkv, b_qkv, qw, qb, kw, kb,
                         Cc, 3*Cc, bm, bn, sm);
        } else {
            int b2 = t - 512;
            int bn = (b2 & 15) * GBN;
            int bm = (b2 >> 4) * GBM;
            gemm_v_tile(g_xh, g_xl, g_wvh, g_wvl, b_qkv + 2*Cc,
                        K2c, Cc, bm, bn, sm);
        }
        __syncthreads();   // protect smem reuse across persistent tiles
    }
}

// =============== standalone bf16 GEMM (proj) ==============================
__global__ __launch_bounds__(256, 3) void gemm_bf16_pre_kernel(
    const uint32_t* __restrict__ Ah, const uint32_t* __restrict__ Al,
    const uint32_t* __restrict__ Bh, const uint32_t* __restrict__ Bl,
    const float* __restrict__ bias, float* __restrict__ C,
    int K2, int N, int ldc)
{
    __shared__ uint32_t sm[SMEM_U32_TOTAL];
    uint32_t* Ahs = sm;
    uint32_t* Als = sm + 2*HATILE2;
    uint32_t* Bhs = sm + 4*HATILE2;
    uint32_t* Bls = sm + 4*HATILE2 + 2*HBTILE;
    const int bm = blockIdx.y * GBM;
    const int bn = blockIdx.x * GBN;
    const int tid  = threadIdx.x;
    const int lane = tid & 31;
    const int warp = tid >> 5;
    const int warpM = warp & 3;
    const int warpN = warp >> 2;
    const int g  = lane >> 2;
    const int tq = lane & 3;

    const int aRow = tid >> 1;
    const int aQ   = (tid & 1) * 4;
    const int bSel = tid >> 7;
    const int bT   = tid & 127;
    const int bRow = bT >> 4;
    const int bQ   = (bT & 15) * 4;

    const uint32_t ah_u = (uint32_t)__cvta_generic_to_shared(Ahs);
    const uint32_t al_u = (uint32_t)__cvta_generic_to_shared(Als);
    const uint32_t bh_u = (uint32_t)__cvta_generic_to_shared(Bhs);
    const uint32_t bl_u = (uint32_t)__cvta_generic_to_shared(Bls);

    float acc[2][4][4];
#pragma unroll
    for (int mf = 0; mf < 2; mf++)
#pragma unroll
        for (int nf = 0; nf < 4; nf++)
#pragma unroll
            for (int r = 0; r < 4; r++) acc[mf][nf][r] = 0.f;

    const int nIter = K2 / 8;

    {
        const uint32_t* gah = Ah + (size_t)(bm + aRow) * K2 + aQ;
        const uint32_t* gal = Al + (size_t)(bm + aRow) * K2 + aQ;
        uint32_t sa = (aRow*HASTR2 + aQ) * 4;
        CP_ASYNC16(ah_u + sa, gah);
        CP_ASYNC16(al_u + sa, gal);
        const uint32_t* gb = (bSel ? Bl : Bh) + (size_t)bRow * N + bn + bQ;
        uint32_t sb = (bSel ? bl_u : bh_u) + (bRow*HBSTR + bQ) * 4;
        CP_ASYNC16(sb, gb);
        CP_COMMIT();
    }

    for (int it = 0; it < nIter; it++) {
        const int buf = it & 1;
        const bool more = (it + 1 < nIter);
        if (more) {
            int k2o = (it + 1) * 8;
            int nbuf = buf ^ 1;
            const uint32_t* gah = Ah + (size_t)(bm + aRow) * K2 + k2o + aQ;
            const uint32_t* gal = Al + (size_t)(bm + aRow) * K2 + k2o + aQ;
            uint32_t sa = (nbuf*HATILE2 + aRow*HASTR2 + aQ) * 4;
            CP_ASYNC16(ah_u + sa, gah);
            CP_ASYNC16(al_u + sa, gal);
            const uint32_t* gb = (bSel ? Bl : Bh) + (size_t)(k2o + bRow) * N + bn + bQ;
            uint32_t sb = (bSel ? bl_u : bh_u) + (nbuf*HBTILE + bRow*HBSTR + bQ) * 4;
            CP_ASYNC16(sb, gb);
            CP_COMMIT();
            CP_WAIT1();
        } else {
            CP_WAIT0();
        }
        __syncthreads();

        const uint32_t* ahs = Ahs + buf*HATILE2;
        const uint32_t* als = Als + buf*HATILE2;
        const uint32_t* bhs = Bhs + buf*HBTILE;
        const uint32_t* bls = Bls + buf*HBTILE;

        uint32_t ah[2][4], al[2][4];
#pragma unroll
        for (int mf = 0; mf < 2; mf++) {
            const int m = warpM * 32 + mf * 16 + g;
            ah[mf][0] = ahs[m*HASTR2 + tq];
            ah[mf][1] = ahs[(m+8)*HASTR2 + tq];
            ah[mf][2] = ahs[m*HASTR2 + tq + 4];
            ah[mf][3] = ahs[(m+8)*HASTR2 + tq + 4];
            al[mf][0] = als[m*HASTR2 + tq];
            al[mf][1] = als[(m+8)*HASTR2 + tq];
            al[mf][2] = als[m*HASTR2 + tq + 4];
            al[mf][3] = als[(m+8)*HASTR2 + tq + 4];
        }
        uint32_t bh[4][2], bl[4][2];
#pragma unroll
        for (int nf = 0; nf < 4; nf++) {
            const int n = warpN * 32 + nf * 8 + g;
            bh[nf][0] = bhs[tq*HBSTR + n];
            bh[nf][1] = bhs[(tq+4)*HBSTR + n];
            bl[nf][0] = bls[tq*HBSTR + n];
            bl[nf][1] = bls[(tq+4)*HBSTR + n];
        }
#pragma unroll
        for (int mf = 0; mf < 2; mf++)
#pragma unroll
            for (int nf = 0; nf < 4; nf++) mma_bf16(acc[mf][nf], ah[mf], bh[nf]);
#pragma unroll
        for (int mf = 0; mf < 2; mf++)
#pragma unroll
            for (int nf = 0; nf < 4; nf++) mma_bf16(acc[mf][nf], al[mf], bh[nf]);
#pragma unroll
        for (int mf = 0; mf < 2; mf++)
#pragma unroll
            for (int nf = 0; nf < 4; nf++) mma_bf16(acc[mf][nf], ah[mf], bl[nf]);

        __syncthreads();
    }

#pragma unroll
    for (int mf = 0; mf < 2; mf++) {
#pragma unroll
        for (int nf = 0; nf < 4; nf++) {
            const int r0 = bm + warpM * 32 + mf * 16 + g;
            const int c0 = bn + warpN * 32 + nf * 8 + tq * 2;
            float2 bv = *reinterpret_cast<const float2*>(bias + c0);
            float2 o0 = make_float2(acc[mf][nf][0] + bv.x, acc[mf][nf][1] + bv.y);
            float2 o1 = make_float2(acc[mf][nf][2] + bv.x, acc[mf][nf][3] + bv.y);
            *reinterpret_cast<float2*>(C + (size_t)r0 * ldc + c0)       = o0;
            *reinterpret_cast<float2*>(C + (size_t)(r0 + 8) * ldc + c0) = o1;
        }
    }
}

// ------------- compressed keys: mean pool over BLK=8 ---------------------
__global__ __launch_bounds__(64) void kcmp_kernel()
{
    int bhm = blockIdx.x;
    int d = threadIdx.x;
    int bh = bhm / NBc, m = bhm % NBc;
    const float* kr = g_k + ((size_t)bh*Nn + m*BLKc) * Dd;
    float s = 0.f;
#pragma unroll
    for (int t = 0; t < BLKc; t++) s += kr[t*Dd + d];
    g_kcmp[(size_t)bhm*Dd + d] = s * (1.f/BLKc);
}

// ------------- kv/z partials ----------------------------------------------
__global__ __launch_bounds__(256) void kv_chunk_kernel()
{
    int bh = blockIdx.x;
    int ch = blockIdx.y;
    int tid = threadIdx.x;
    int e = tid & 63;
    int dg = tid >> 6;
    __shared__ float sh[4][128];
    float acc[16];
#pragma unroll
    for (int j = 0; j < 16; j++) acc[j] = 0.f;
    float zacc = 0.f;
    size_t base = (size_t)bh * Nn * Dd;
    const int lr = tid >> 6;
    const int lc = (tid & 63) * 2;
    for (int i0 = 0; i0 < CHLEN; i0 += 4) {
        __syncthreads();
        {
            int n = ch * CHLEN + i0 + lr;
            float2 val;
            if (lc < 64)
                val = *reinterpret_cast<const float2*>(g_pk + base + (size_t)n*Dd + lc);
            else
                val = *reinterpret_cast<const float2*>(g_v + base + (size_t)n*Dd + (lc - 64));
            sh[lr][lc]   = val.x;
            sh[lr][lc+1] = val.y;
        }
        __syncthreads();
#pragma unroll
        for (int r = 0; r < 4; r++) {
            float ve = sh[r][64 + e];
#pragma unroll
            for (int j = 0; j < 16; j++) acc[j] += sh[r][dg*16 + j] * ve;
            if (tid < 64) zacc += sh[r][tid];
        }
    }
    float* out = g_kvp + ((size_t)ch * BHc + bh) * (Dd*Dd);
#pragma unroll
    for (int j = 0; j < 16; j++) out[(dg*16 + j)*Dd + e] = acc[j];
    if (tid < 64) g_zp[((size_t)ch * BHc + bh) * Dd + tid] = zacc;
}

__global__ __launch_bounds__(256) void kv_reduce_kernel()
{
    int idx = blockIdx.x * 256 + threadIdx.x;
    const int KVN = BHc*Dd*Dd;
    const int ZN  = BHc*Dd;
    if (idx < KVN) {
        float s = 0.f;
#pragma unroll
        for (int c = 0; c < NCHUNK; c++) s += g_kvp[(size_t)c*KVN + idx];
        g_kv[idx] = s;
    } else if (idx < KVN + ZN) {
        int z = idx - KVN;
        float s = 0.f;
#pragma unroll
        for (int c = 0; c < NCHUNK; c++) s += g_zp[(size_t)c*ZN + z];
        g_z[z] = s;
    }
}

// ------------- router + top-7 : smem-transposed kcmp ---------------------
#define KCSTR 132
__global__ __launch_bounds__(256) void router_topk_kernel()
{
    __shared__ float kct[Dd * KCSTR];
    int bh = blockIdx.x >> 4;
    int n0 = (blockIdx.x & 15) * 64;
    int tid = threadIdx.x;
    int warp = tid >> 5, lane = tid & 31;

    const float* kc = g_kcmp + (size_t)bh * NBc * Dd;
#pragma unroll
    for (int i = 0; i < 32; i++) {
        int idx = tid + i * 256;
        int blk = idx >> 6, d = idx & 63;
        kct[d * KCSTR + blk] = kc[idx];
    }
    __syncthreads();

    const float scale = 0.125f;
    const float NEGINF = -__int_as_float(0x7f800000);

    for (int qi = 0; qi < 8; qi++) {
        int n = n0 + warp * 8 + qi;
        const float* qrow = g_q + ((size_t)bh*Nn + n) * Dd;
        float q0 = qrow[lane], q1 = qrow[lane + 32];
        float s0 = 0.f, s1 = 0.f, s2 = 0.f, s3 = 0.f;
#pragma unroll
        for (int d = 0; d < 64; d++) {
            float qd = (d < 32) ? __shfl_sync(~0u, q0, d)
                                : __shfl_sync(~0u, q1, d - 32);
            float4 kv4 = *reinterpret_cast<const float4*>(&kct[d * KCSTR + lane * 4]);
            s0 += qd * kv4.x; s1 += qd * kv4.y;
            s2 += qd * kv4.z; s3 += qd * kv4.w;
        }
        s0 *= scale; s1 *= scale; s2 *= scale; s3 *= scale;

        int qidx = bh * Nn + n;
#pragma unroll
        for (int r = 0; r < TOPKc; r++) {
            float bv = s0; int bj = 0;
            if (s1 > bv) { bv = s1; bj = 1; }
            if (s2 > bv) { bv = s2; bj = 2; }
            if (s3 > bv) { bv = s3; bj = 3; }
            int bm = lane * 4 + bj;
#pragma unroll
            for (int o = 16; o; o >>= 1) {
                float ov = __shfl_xor_sync(~0u, bv, o);
                int   om = __shfl_xor_sync(~0u, bm, o);
                if (ov > bv || (ov == bv && om < bm)) { bv = ov; bm = om; }
            }
            if ((bm >> 2) == lane) {
                int j = bm & 3;
                if      (j == 0) s0 = NEGINF;
                else if (j == 1) s1 = NEGINF;
                else if (j == 2) s2 = NEGINF;
                else             s3 = NEGINF;
            }
            if (lane == 0) g_topk[(size_t)qidx*TOPKc + r] = bm;
        }
    }
}

// ------------- fused sparse softmax attention + linear branch ------------
__global__ __launch_bounds__(256) void attn_kernel()
{
    int bh = blockIdx.x / (Nn/8);
    int b = bh / Hh, h = bh % Hh;
    int n0 = (blockIdx.x % (Nn/8)) * 8;
    int warp = threadIdx.x >> 5;
    int lane = threadIdx.x & 31;
    int n = n0 + warp;
    __shared__ float sq  [8][64];
    __shared__ float spq [8][64];
    __shared__ float sp  [8][64];
    __shared__ float slog[8][64];
    __shared__ int   sblk[8][8];

    size_t qb = ((size_t)bh*Nn + n) * Dd;
    {
        float2 a = *reinterpret_cast<const float2*>(g_q  + qb + lane*2);
        float2 c = *reinterpret_cast<const float2*>(g_pq + qb + lane*2);
        sq [warp][lane*2] = a.x; sq [warp][lane*2+1] = a.y;
        spq[warp][lane*2] = c.x; spq[warp][lane*2+1] = c.y;
    }
    if (lane < TOPKc) sblk[warp][lane] = g_topk[((size_t)bh*Nn + n)*TOPKc + lane];
    __syncwarp();

    const float scale = 0.125f;
    const int NSEL = TOPKc * BLKc;   // 56
    const float NEGINF = -__int_as_float(0x7f800000);
    const float4* sq4 = reinterpret_cast<const float4*>(sq[warp]);
    const size_t kbase = (size_t)bh * Nn * Dd;
    const int seg = lane & 15;
    float4 qv = sq4[seg];

#pragma unroll 4
    for (int i = 0; i < NSEL/2; i++) {
        int s = 2*i + (lane >> 4);
        int tok = sblk[warp][s >> 3] * BLKc + (s & 7);
        float4 kv = __ldg(reinterpret_cast<const float4*>(g_k + kbase + (size_t)tok * Dd) + seg);
        float a = qv.x*kv.x + qv.y*kv.y + qv.z*kv.z + qv.w*kv.w;
#pragma unroll
        for (int o = 8; o; o >>= 1) a += __shfl_xor_sync(~0u, a, o);
        if (seg == 0) slog[warp][s] = a;
    }
    __syncwarp();

    float l0 = slog[warp][lane] * scale;
    float l1 = (lane + 32 < NSEL) ? slog[warp][lane + 32] * scale : NEGINF;
    float mx = fmaxf(l0, l1);
#pragma unroll
    for (int o = 16; o; o >>= 1) mx = fmaxf(mx, __shfl_xor_sync(~0u, mx, o));
    float e0 = __expf(l0 - mx);
    float e1 = (lane + 32 < NSEL) ? __expf(l1 - mx) : 0.f;
    float se = e0 + e1;
#pragma unroll
    for (int o = 16; o; o >>= 1) se += __shfl_xor_sync(~0u, se, o);
    float inv = 1.f / se;
    sp[warp][lane]      = e0 * inv;
    sp[warp][lane + 32] = e1 * inv;
    __syncwarp();

    const int dd = lane * 2;
    float a0 = 0.f, a1 = 0.f;
#pragma unroll 8
    for (int s = 0; s < NSEL; s++) {
        int tok = sblk[warp][s >> 3] * BLKc + (s & 7);
        float2 vv = *reinterpret_cast<const float2*>(g_v + kbase + (size_t)tok * Dd + dd);
        float p = sp[warp][s];
        a0 += p * vv.x;
        a1 += p * vv.y;
    }

    const float* zr = g_z + (size_t)bh * Dd;
    float pq0 = spq[warp][dd], pq1 = spq[warp][dd + 1];
    float t = pq0 * zr[dd] + pq1 * zr[dd + 1];
#pragma unroll
    for (int o = 16; o; o >>= 1) t += __shfl_xor_sync(~0u, t, o);
    float inv_den = 1.f / (t + 1e-6f);
    const float* kvm = g_kv + (size_t)bh * Dd * Dd;
    float n0a = 0.f, n1a = 0.f;
#pragma unroll
    for (int e = 0; e < 64; e++) {
        float pe = spq[warp][e];
        float2 kv2 = *reinterpret_cast<const float2*>(kvm + e*Dd + dd);
        n0a += pe * kv2.x;
        n1a += pe * kv2.y;
    }
    // epilogue: split to bf16 hi/lo planes directly (pair = dims dd, dd+1)
    float o0 = a0 + n0a * inv_den;
    float o1 = a1 + n1a * inv_den;
    uint32_t ph, pl;
    bf16_split2(o0, o1, ph, pl);
    size_t pidx = ((size_t)(b*Nn + n)) * K2c + (h*Dd + dd)/2;
    g_ah[pidx] = ph;
    g_al[pidx] = pl;
}

// ---------------------------------------------------------------------------
extern "C" void kernel_launch(void* const* d_in, const int* in_sizes, int n_in,
                              void* d_out, int out_size)
{
    const float* x      = (const float*)d_in[0];
    const float* w_qkv  = (const float*)d_in[1];
    const float* b_qkv  = (const float*)d_in[2];
    const float* qw     = (const float*)d_in[3];
    const float* qb     = (const float*)d_in[4];
    const float* kw     = (const float*)d_in[5];
    const float* kb     = (const float*)d_in[6];
    const float* w_proj = (const float*)d_in[7];
    const float* b_proj = (const float*)d_in[8];
    float* out = (float*)d_out;

    void *p_xh, *p_xl, *p_ah, *p_al, *p_wvh, *p_wvl, *p_wph, *p_wpl;
    cudaGetSymbolAddress(&p_xh, g_xh);   cudaGetSymbolAddress(&p_xl, g_xl);
    cudaGetSymbolAddress(&p_ah, g_ah);   cudaGetSymbolAddress(&p_al, g_al);
    cudaGetSymbolAddress(&p_wvh, g_wvh); cudaGetSymbolAddress(&p_wvl, g_wvl);
    cudaGetSymbolAddress(&p_wph, g_wph); cudaGetSymbolAddress(&p_wpl, g_wpl);

    const int M = Bb*Nn;               // 2048

    // 0) bf16 splits: x (A operand), w_qkv v-cols, w_proj
    split_a_kernel<<<(M*K2c)/256, 256>>>(x, (uint32_t*)p_xh, (uint32_t*)p_xl, M*K2c);
    split_b_kernel<<<(K2c*Cc)/256, 256>>>(w_qkv + 2*Cc, (uint32_t*)p_wvh, (uint32_t*)p_wvl, 3*Cc);
    split_b_kernel<<<(K2c*Cc)/256, 256>>>(w_proj, (uint32_t*)p_wph, (uint32_t*)p_wpl, Cc);

    // 1) persistent fused QKV + LN + phi (444 blocks over 768 tiles)
    qkv_mega_kernel<<<PERSIST_GRID, 256>>>(x, w_qkv, b_qkv, qw, qb, kw, kb);

    // 2) compressed keys
    kcmp_kernel<<<BHc*NBc, 64>>>();
    // 3) kv / z
    {
        dim3 grid(BHc, NCHUNK);
        kv_chunk_kernel<<<grid, 256>>>();
        int total = BHc*Dd*Dd + BHc*Dd;
        kv_reduce_kernel<<<(total + 255)/256, 256>>>();
    }
    // 4) router + topk
    router_topk_kernel<<<BHc*(Nn/64), 256>>>();
    // 5) sparse + linear attention (writes bf16 planes for proj)
    attn_kernel<<<BHc*(Nn/8), 256>>>();
    // 6) proj GEMM (3xbf16) directly from attn's planes
    {
        dim3 grid(Cc/GBN, M/GBM);
        gemm_bf16_pre_kernel<<<grid, 256>>>((const uint32_t*)p_ah, (const uint32_t*)p_al,
                                            (const uint32_t*)p_wph, (const uint32_t*)p_wpl,
                                            b_proj, out, K2c, Cc, Cc);
    }
    (void)in_sizes; (void)n_in; (void)out_size;
}

// round 17
// speedup vs baseline: 1.0796x; 1.0796x over previous
#include <cuda_runtime.h>
#include <math.h>
#include <stdint.h>

// Problem constants
#define Bb   2
#define Nn   1024
#define Cc   1024
#define Hh   16
#define Dd   64
#define BLKc 8
#define NBc  128
#define TOPKc 7
#define BHc  (Bb*Hh)          // 32
#define NCHUNK 32
#define CHLEN (Nn/NCHUNK)     // 32
#define K2c  (Cc/2)           // 512 bf16-pair columns

// ---------------- scratch (device globals; no allocation) ----------------
__device__ __align__(16) float g_q   [BHc*Nn*Dd];
__device__ __align__(16) float g_k   [BHc*Nn*Dd];
__device__ __align__(16) float g_v   [BHc*Nn*Dd];
__device__ __align__(16) float g_pq  [BHc*Nn*Dd];
__device__ __align__(16) float g_pk  [BHc*Nn*Dd];
__device__ __align__(16) float g_kcmp[BHc*NBc*Dd];
__device__               int   g_topk[BHc*Nn*TOPKc];
__device__ __align__(16) float g_kvp [NCHUNK*BHc*Dd*Dd];
__device__ __align__(16) float g_zp  [NCHUNK*BHc*Dd];
__device__ __align__(16) float g_kv  [BHc*Dd*Dd];
__device__ __align__(16) float g_z   [BHc*Dd];
// bf16 hi/lo packed pair operands
__device__ __align__(16) uint32_t g_xh [Bb*Nn*K2c];
__device__ __align__(16) uint32_t g_xl [Bb*Nn*K2c];
__device__ __align__(16) uint32_t g_ah [Bb*Nn*K2c];   // attn output planes
__device__ __align__(16) uint32_t g_al [Bb*Nn*K2c];
__device__ __align__(16) uint32_t g_wvh[K2c*Cc];
__device__ __align__(16) uint32_t g_wvl[K2c*Cc];
__device__ __align__(16) uint32_t g_wph[K2c*Cc];
__device__ __align__(16) uint32_t g_wpl[K2c*Cc];

// ---------------- helpers -------------------------------------------------
__device__ __forceinline__ uint32_t f2tf32(float x) {
    uint32_t r;
    asm("cvt.rna.tf32.f32 %0, %1;" : "=r"(r) : "f"(x));
    return r;
}

__device__ __forceinline__ void bf16_split2(float x0, float x1,
                                            uint32_t& ph, uint32_t& pl) {
    uint32_t h;
    asm("cvt.rn.bf16x2.f32 %0, %1, %2;" : "=r"(h) : "f"(x1), "f"(x0));
    float h0 = __uint_as_float(h << 16);
    float h1 = __uint_as_float(h & 0xffff0000u);
    float r0 = x0 - h0, r1 = x1 - h1;
    uint32_t l;
    asm("cvt.rn.bf16x2.f32 %0, %1, %2;" : "=r"(l) : "f"(r1), "f"(r0));
    ph = h; pl = l;
}

__device__ __forceinline__ void mma_tf32(float* d, const uint32_t* a, const uint32_t* b) {
    asm volatile(
        "mma.sync.aligned.m16n8k8.row.col.f32.tf32.tf32.f32 "
        "{%0,%1,%2,%3}, {%4,%5,%6,%7}, {%8,%9}, {%0,%1,%2,%3};"
        : "+f"(d[0]), "+f"(d[1]), "+f"(d[2]), "+f"(d[3])
        : "r"(a[0]), "r"(a[1]), "r"(a[2]), "r"(a[3]), "r"(b[0]), "r"(b[1]));
}

__device__ __forceinline__ void mma_bf16(float* d, const uint32_t* a, const uint32_t* b) {
    asm volatile(
        "mma.sync.aligned.m16n8k16.row.col.f32.bf16.bf16.f32 "
        "{%0,%1,%2,%3}, {%4,%5,%6,%7}, {%8,%9}, {%0,%1,%2,%3};"
        : "+f"(d[0]), "+f"(d[1]), "+f"(d[2]), "+f"(d[3])
        : "r"(a[0]), "r"(a[1]), "r"(a[2]), "r"(a[3]), "r"(b[0]), "r"(b[1]));
}

#define CP_ASYNC16(saddr, gptr) \
    asm volatile("cp.async.cg.shared.global [%0], [%1], 16;" :: "r"(saddr), "l"(gptr))
#define CP_COMMIT() asm volatile("cp.async.commit_group;")
#define CP_WAIT1()  asm volatile("cp.async.wait_group 1;")
#define CP_WAIT0()  asm volatile("cp.async.wait_group 0;")

// ---------------- fused bf16 split kernel (one launch) --------------------
// regions: [0,4096) x pairs | [4096,6144) w_qkv v-cols | [6144,8192) w_proj
__global__ __launch_bounds__(256) void split_mega_kernel(
    const float* __restrict__ x, const float* __restrict__ w_qkv,
    const float* __restrict__ w_proj)
{
    int b = blockIdx.x;
    int tid = threadIdx.x;
    if (b < 4096) {
        int i = b * 256 + tid;
        float2 v = reinterpret_cast<const float2*>(x)[i];
        uint32_t h, l;
        bf16_split2(v.x, v.y, h, l);
        g_xh[i] = h; g_xl[i] = l;
    } else if (b < 6144) {
        int i = (b - 4096) * 256 + tid;
        int k2 = i >> 10, n = i & 1023;
        float x0 = w_qkv[(size_t)(2*k2)   * (3*Cc) + 2*Cc + n];
        float x1 = w_qkv[(size_t)(2*k2+1) * (3*Cc) + 2*Cc + n];
        uint32_t h, l;
        bf16_split2(x0, x1, h, l);
        g_wvh[i] = h; g_wvl[i] = l;
    } else {
        int i = (b - 6144) * 256 + tid;
        int k2 = i >> 10, n = i & 1023;
        float x0 = w_proj[(size_t)(2*k2)   * Cc + n];
        float x1 = w_proj[(size_t)(2*k2+1) * Cc + n];
        uint32_t h, l;
        bf16_split2(x0, x1, h, l);
        g_wph[i] = h; g_wpl[i] = l;
    }
}

// =============== GEMM tile device functions (cp.async staging) ============
#define GBM 128
#define GBN 64
#define GBK 16
#define ASTR2 20
#define ATILE2 (GBM*ASTR2)   // 2560 floats per buf
#define BSTR 72
#define BTILE (GBK*BSTR)     // 1152
#define HASTR2 12
#define HATILE2 (GBM*HASTR2) // 1536 u32 per buf
#define HBSTR 72
#define HBTILE (8*HBSTR)     // 576
// epilogue staging tile: 128 x 66 floats = 8448 (also >= mainloop needs)
#define SMEM_U32_TOTAL 8448
#define EPSTR 66

// ---- 3xTF32 q/k tile: R13 double-buffer mainloop; epilogue = LN + phi ----
__device__ __forceinline__ void gemm_qk_tile(
    const float* __restrict__ A, const float* __restrict__ B,
    const float* __restrict__ bias,
    const float* __restrict__ qw, const float* __restrict__ qb,
    const float* __restrict__ kw, const float* __restrict__ kb,
    int K, int ldb, int bm, int bn, uint32_t* smraw)
{
    float* As = reinterpret_cast<float*>(smraw);
    float* Bs = reinterpret_cast<float*>(smraw + 2*ATILE2);
    const int tid  = threadIdx.x;
    const int lane = tid & 31;
    const int warp = tid >> 5;
    const int warpM = warp & 3;
    const int warpN = warp >> 2;
    const int g  = lane >> 2;
    const int tq = lane & 3;

    const int aRow = tid >> 1;
    const int aQf  = (tid & 1) * 8;
    const int bRow = tid >> 4;
    const int bQf  = (tid & 15) * 4;

    const uint32_t as_u = (uint32_t)__cvta_generic_to_shared(As);
    const uint32_t bs_u = (uint32_t)__cvta_generic_to_shared(Bs);

    float acc[2][4][4];
#pragma unroll
    for (int mf = 0; mf < 2; mf++)
#pragma unroll
        for (int nf = 0; nf < 4; nf++)
#pragma unroll
            for (int r = 0; r < 4; r++) acc[mf][nf][r] = 0.f;

    const int nIter = K / GBK;

    {
        const float* ga = A + (size_t)(bm + aRow) * K + aQf;
        uint32_t sa = as_u + (aRow*ASTR2 + aQf) * 4;
        CP_ASYNC16(sa, ga);
        CP_ASYNC16(sa + 16, ga + 4);
        const float* gb = B + (size_t)bRow * ldb + bn + bQf;
        uint32_t sb = bs_u + (bRow*BSTR + bQf) * 4;
        CP_ASYNC16(sb, gb);
        CP_COMMIT();
    }

    for (int it = 0; it < nIter; it++) {
        const int buf = it & 1;
        const bool more = (it + 1 < nIter);
        if (more) {
            int k0 = (it + 1) * GBK;
            int nbuf = buf ^ 1;
            const float* ga = A + (size_t)(bm + aRow) * K + k0 + aQf;
            uint32_t sa = as_u + (nbuf*ATILE2 + aRow*ASTR2 + aQf) * 4;
            CP_ASYNC16(sa, ga);
            CP_ASYNC16(sa + 16, ga + 4);
            const float* gb = B + (size_t)(k0 + bRow) * ldb + bn + bQf;
            uint32_t sb = bs_u + (nbuf*BTILE + bRow*BSTR + bQf) * 4;
            CP_ASYNC16(sb, gb);
            CP_COMMIT();
            CP_WAIT1();
        } else {
            CP_WAIT0();
        }
        __syncthreads();

        const float* as = As + buf*ATILE2;
        const float* bs = Bs + buf*BTILE;
#pragma unroll
        for (int ks = 0; ks < 2; ks++) {
            const int kb = ks * 8;
            uint32_t ahi[2][4], alo[2][4];
#pragma unroll
            for (int mf = 0; mf < 2; mf++) {
                const int m = warpM * 32 + mf * 16 + g;
                float v0 = as[m*ASTR2 + kb + tq];
                float v1 = as[(m+8)*ASTR2 + kb + tq];
                float v2 = as[m*ASTR2 + kb + tq + 4];
                float v3 = as[(m+8)*ASTR2 + kb + tq + 4];
                ahi[mf][0] = f2tf32(v0); alo[mf][0] = f2tf32(v0 - __uint_as_float(ahi[mf][0]));
                ahi[mf][1] = f2tf32(v1); alo[mf][1] = f2tf32(v1 - __uint_as_float(ahi[mf][1]));
                ahi[mf][2] = f2tf32(v2); alo[mf][2] = f2tf32(v2 - __uint_as_float(ahi[mf][2]));
                ahi[mf][3] = f2tf32(v3); alo[mf][3] = f2tf32(v3 - __uint_as_float(ahi[mf][3]));
            }
            uint32_t bhi[4][2], blo[4][2];
#pragma unroll
            for (int nf = 0; nf < 4; nf++) {
                const int n = warpN * 32 + nf * 8 + g;
                float v0 = bs[(kb + tq) * BSTR + n];
                float v1 = bs[(kb + tq + 4) * BSTR + n];
                bhi[nf][0] = f2tf32(v0); blo[nf][0] = f2tf32(v0 - __uint_as_float(bhi[nf][0]));
                bhi[nf][1] = f2tf32(v1); blo[nf][1] = f2tf32(v1 - __uint_as_float(bhi[nf][1]));
            }
#pragma unroll
            for (int mf = 0; mf < 2; mf++)
#pragma unroll
                for (int nf = 0; nf < 4; nf++) mma_tf32(acc[mf][nf], ahi[mf], bhi[nf]);
#pragma unroll
            for (int mf = 0; mf < 2; mf++)
#pragma unroll
                for (int nf = 0; nf < 4; nf++) mma_tf32(acc[mf][nf], alo[mf], bhi[nf]);
#pragma unroll
            for (int mf = 0; mf < 2; mf++)
#pragma unroll
                for (int nf = 0; nf < 4; nf++) mma_tf32(acc[mf][nf], ahi[mf], blo[nf]);
        }
        __syncthreads();
    }

    // ---- epilogue: stage acc+bias into smem, then LN + phi per row ----
    float* so = reinterpret_cast<float*>(smraw);   // 128 x EPSTR
#pragma unroll
    for (int mf = 0; mf < 2; mf++) {
#pragma unroll
        for (int nf = 0; nf < 4; nf++) {
            int lr = warpM * 32 + mf * 16 + g;
            int lc = warpN * 32 + nf * 8 + tq * 2;
            float2 bv = *reinterpret_cast<const float2*>(bias + bn + lc);
            so[lr*EPSTR + lc]       = acc[mf][nf][0] + bv.x;
            so[lr*EPSTR + lc + 1]   = acc[mf][nf][1] + bv.y;
            so[(lr+8)*EPSTR + lc]   = acc[mf][nf][2] + bv.x;
            so[(lr+8)*EPSTR + lc+1] = acc[mf][nf][3] + bv.y;
        }
    }
    __syncthreads();

    const int slot = bn >> 6;              // 0..31
    const bool isq = slot < 16;
    const int h = isq ? slot : slot - 16;
    const float* lw = isq ? qw : kw;
    const float* lb = isq ? qb : kb;
    float* gv = isq ? g_q : g_k;
    float* gp = isq ? g_pq : g_pk;
    const int d0 = lane, d1 = lane + 32;
    const float wd0 = lw[d0], wd1 = lw[d1];
    const float bd0 = lb[d0], bd1 = lb[d1];

    for (int rr = 0; rr < 16; rr++) {
        int row = warp * 16 + rr;
        int mtok = bm + row;
        int btok = mtok >> 10, n = mtok & 1023;
        size_t obase = ((size_t)(btok*Hh + h) * Nn + n) * Dd;
        float v0 = so[row*EPSTR + d0];
        float v1 = so[row*EPSTR + d1];
        float s = v0 + v1;
#pragma unroll
        for (int o = 16; o; o >>= 1) s += __shfl_xor_sync(~0u, s, o);
        float m = s * (1.f/64.f);
        float a0 = v0 - m, a1 = v1 - m;
        float vs = a0*a0 + a1*a1;
#pragma unroll
        for (int o = 16; o; o >>= 1) vs += __shfl_xor_sync(~0u, vs, o);
        float r = rsqrtf(vs * (1.f/64.f) + 1e-6f);
        float y0 = a0*r*wd0 + bd0;
        float y1 = a1*r*wd1 + bd1;
        gv[obase + d0] = y0; gv[obase + d1] = y1;
        float mx = fmaxf(y0, y1);
#pragma unroll
        for (int o = 16; o; o >>= 1) mx = fmaxf(mx, __shfl_xor_sync(~0u, mx, o));
        float e0 = __expf(y0 - mx), e1 = __expf(y1 - mx);
        float se = e0 + e1;
#pragma unroll
        for (int o = 16; o; o >>= 1) se += __shfl_xor_sync(~0u, se, o);
        float inv = 1.f / se;
        gp[obase + d0] = e0*inv; gp[obase + d1] = e1*inv;
    }
}

// ---- pre-split 3xbf16 v tile: R13 mainloop; epilogue scatters g_v --------
__device__ __forceinline__ void gemm_v_tile(
    const uint32_t* __restrict__ Ah, const uint32_t* __restrict__ Al,
    const uint32_t* __restrict__ Bh, const uint32_t* __restrict__ Bl,
    const float* __restrict__ bias,
    int K2, int N, int bm, int bn, uint32_t* smraw)
{
    uint32_t* Ahs = smraw;
    uint32_t* Als = smraw + 2*HATILE2;
    uint32_t* Bhs = smraw + 4*HATILE2;
    uint32_t* Bls = smraw + 4*HATILE2 + 2*HBTILE;
    const int tid  = threadIdx.x;
    const int lane = tid & 31;
    const int warp = tid >> 5;
    const int warpM = warp & 3;
    const int warpN = warp >> 2;
    const int g  = lane >> 2;
    const int tq = lane & 3;

    const int aRow = tid >> 1;
    const int aQ   = (tid & 1) * 4;
    const int bSel = tid >> 7;
    const int bT   = tid & 127;
    const int bRow = bT >> 4;
    const int bQ   = (bT & 15) * 4;

    const uint32_t ah_u = (uint32_t)__cvta_generic_to_shared(Ahs);
    const uint32_t al_u = (uint32_t)__cvta_generic_to_shared(Als);
    const uint32_t bh_u = (uint32_t)__cvta_generic_to_shared(Bhs);
    const uint32_t bl_u = (uint32_t)__cvta_generic_to_shared(Bls);

    float acc[2][4][4];
#pragma unroll
    for (int mf = 0; mf < 2; mf++)
#pragma unroll
        for (int nf = 0; nf < 4; nf++)
#pragma unroll
            for (int r = 0; r < 4; r++) acc[mf][nf][r] = 0.f;

    const int nIter = K2 / 8;

    {
        const uint32_t* gah = Ah + (size_t)(bm + aRow) * K2 + aQ;
        const uint32_t* gal = Al + (size_t)(bm + aRow) * K2 + aQ;
        uint32_t sa = (aRow*HASTR2 + aQ) * 4;
        CP_ASYNC16(ah_u + sa, gah);
        CP_ASYNC16(al_u + sa, gal);
        const uint32_t* gb = (bSel ? Bl : Bh) + (size_t)bRow * N + bn + bQ;
        uint32_t sb = (bSel ? bl_u : bh_u) + (bRow*HBSTR + bQ) * 4;
        CP_ASYNC16(sb, gb);
        CP_COMMIT();
    }

    for (int it = 0; it < nIter; it++) {
        const int buf = it & 1;
        const bool more = (it + 1 < nIter);
        if (more) {
            int k2o = (it + 1) * 8;
            int nbuf = buf ^ 1;
            const uint32_t* gah = Ah + (size_t)(bm + aRow) * K2 + k2o + aQ;
            const uint32_t* gal = Al + (size_t)(bm + aRow) * K2 + k2o + aQ;
            uint32_t sa = (nbuf*HATILE2 + aRow*HASTR2 + aQ) * 4;
            CP_ASYNC16(ah_u + sa, gah);
            CP_ASYNC16(al_u + sa, gal);
            const uint32_t* gb = (bSel ? Bl : Bh) + (size_t)(k2o + bRow) * N + bn + bQ;
            uint32_t sb = (bSel ? bl_u : bh_u) + (nbuf*HBTILE + bRow*HBSTR + bQ) * 4;
            CP_ASYNC16(sb, gb);
            CP_COMMIT();
            CP_WAIT1();
        } else {
            CP_WAIT0();
        }
        __syncthreads();

        const uint32_t* ahs = Ahs + buf*HATILE2;
        const uint32_t* als = Als + buf*HATILE2;
        const uint32_t* bhs = Bhs + buf*HBTILE;
        const uint32_t* bls = Bls + buf*HBTILE;

        uint32_t ah[2][4], al[2][4];
#pragma unroll
        for (int mf = 0; mf < 2; mf++) {
            const int m = warpM * 32 + mf * 16 + g;
            ah[mf][0] = ahs[m*HASTR2 + tq];
            ah[mf][1] = ahs[(m+8)*HASTR2 + tq];
            ah[mf][2] = ahs[m*HASTR2 + tq + 4];
            ah[mf][3] = ahs[(m+8)*HASTR2 + tq + 4];
            al[mf][0] = als[m*HASTR2 + tq];
            al[mf][1] = als[(m+8)*HASTR2 + tq];
            al[mf][2] = als[m*HASTR2 + tq + 4];
            al[mf][3] = als[(m+8)*HASTR2 + tq + 4];
        }
        uint32_t bh[4][2], bl[4][2];
#pragma unroll
        for (int nf = 0; nf < 4; nf++) {
            const int n = warpN * 32 + nf * 8 + g;
            bh[nf][0] = bhs[tq*HBSTR + n];
            bh[nf][1] = bhs[(tq+4)*HBSTR + n];
            bl[nf][0] = bls[tq*HBSTR + n];
            bl[nf][1] = bls[(tq+4)*HBSTR + n];
        }
#pragma unroll
        for (int mf = 0; mf < 2; mf++)
#pragma unroll
            for (int nf = 0; nf < 4; nf++) mma_bf16(acc[mf][nf], ah[mf], bh[nf]);
#pragma unroll
        for (int mf = 0; mf < 2; mf++)
#pragma unroll
            for (int nf = 0; nf < 4; nf++) mma_bf16(acc[mf][nf], al[mf], bh[nf]);
#pragma unroll
        for (int mf = 0; mf < 2; mf++)
#pragma unroll
            for (int nf = 0; nf < 4; nf++) mma_bf16(acc[mf][nf], ah[mf], bl[nf]);

        __syncthreads();
    }

    // epilogue: scatter into g_v (B,H,N,D); whole tile is one head (bn/64)
    const int h = bn >> 6;
#pragma unroll
    for (int mf = 0; mf < 2; mf++) {
#pragma unroll
        for (int nf = 0; nf < 4; nf++) {
            const int r0 = bm + warpM * 32 + mf * 16 + g;
            const int c0 = bn + warpN * 32 + nf * 8 + tq * 2;
            const int d = c0 & 63;
            float2 bv = *reinterpret_cast<const float2*>(bias + c0);
            {
                int btok = r0 >> 10, n = r0 & 1023;
                size_t off = ((size_t)(btok*Hh + h) * Nn + n) * Dd + d;
                float2 o0 = make_float2(acc[mf][nf][0] + bv.x, acc[mf][nf][1] + bv.y);
                *reinterpret_cast<float2*>(g_v + off) = o0;
            }
            {
                int r1 = r0 + 8;
                int btok = r1 >> 10, n = r1 & 1023;
                size_t off = ((size_t)(btok*Hh + h) * Nn + n) * Dd + d;
                float2 o1 = make_float2(acc[mf][nf][2] + bv.x, acc[mf][nf][3] + bv.y);
                *reinterpret_cast<float2*>(g_v + off) = o1;
            }
        }
    }
}

// =============== fused QKV kernel: tf32 q,k tiles + bf16 v tiles ==========
__global__ __launch_bounds__(256, 3) void qkv_mega_kernel(
    const float* __restrict__ x, const float* __restrict__ w_qkv,
    const float* __restrict__ b_qkv,
    const float* __restrict__ qw, const float* __restrict__ qb,
    const float* __restrict__ kw, const float* __restrict__ kb)
{
    __shared__ uint32_t sm[SMEM_U32_TOTAL];
    int bid = blockIdx.x;
    if (bid < 512) {
        int bn = (bid & 31) * GBN;
        int bm = (bid >> 5) * GBM;
        gemm_qk_tile(x, w_qkv, b_qkv, qw, qb, kw, kb,
                     Cc, 3*Cc, bm, bn, sm);
    } else {
        int b2 = bid - 512;
        int bn = (b2 & 15) * GBN;
        int bm = (b2 >> 4) * GBM;
        gemm_v_tile(g_xh, g_xl, g_wvh, g_wvl, b_qkv + 2*Cc,
                    K2c, Cc, bm, bn, sm);
    }
}

// =============== standalone bf16 GEMM (proj) ==============================
__global__ __launch_bounds__(256, 3) void gemm_bf16_pre_kernel(
    const uint32_t* __restrict__ Ah, const uint32_t* __restrict__ Al,
    const uint32_t* __restrict__ Bh, const uint32_t* __restrict__ Bl,
    const float* __restrict__ bias, float* __restrict__ C,
    int K2, int N, int ldc)
{
    __shared__ uint32_t sm[SMEM_U32_TOTAL];
    uint32_t* Ahs = sm;
    uint32_t* Als = sm + 2*HATILE2;
    uint32_t* Bhs = sm + 4*HATILE2;
    uint32_t* Bls = sm + 4*HATILE2 + 2*HBTILE;
    const int bm = blockIdx.y * GBM;
    const int bn = blockIdx.x * GBN;
    const int tid  = threadIdx.x;
    const int lane = tid & 31;
    const int warp = tid >> 5;
    const int warpM = warp & 3;
    const int warpN = warp >> 2;
    const int g  = lane >> 2;
    const int tq = lane & 3;

    const int aRow = tid >> 1;
    const int aQ   = (tid & 1) * 4;
    const int bSel = tid >> 7;
    const int bT   = tid & 127;
    const int bRow = bT >> 4;
    const int bQ   = (bT & 15) * 4;

    const uint32_t ah_u = (uint32_t)__cvta_generic_to_shared(Ahs);
    const uint32_t al_u = (uint32_t)__cvta_generic_to_shared(Als);
    const uint32_t bh_u = (uint32_t)__cvta_generic_to_shared(Bhs);
    const uint32_t bl_u = (uint32_t)__cvta_generic_to_shared(Bls);

    float acc[2][4][4];
#pragma unroll
    for (int mf = 0; mf < 2; mf++)
#pragma unroll
        for (int nf = 0; nf < 4; nf++)
#pragma unroll
            for (int r = 0; r < 4; r++) acc[mf][nf][r] = 0.f;

    const int nIter = K2 / 8;

    {
        const uint32_t* gah = Ah + (size_t)(bm + aRow) * K2 + aQ;
        const uint32_t* gal = Al + (size_t)(bm + aRow) * K2 + aQ;
        uint32_t sa = (aRow*HASTR2 + aQ) * 4;
        CP_ASYNC16(ah_u + sa, gah);
        CP_ASYNC16(al_u + sa, gal);
        const uint32_t* gb = (bSel ? Bl : Bh) + (size_t)bRow * N + bn + bQ;
        uint32_t sb = (bSel ? bl_u : bh_u) + (bRow*HBSTR + bQ) * 4;
        CP_ASYNC16(sb, gb);
        CP_COMMIT();
    }

    for (int it = 0; it < nIter; it++) {
        const int buf = it & 1;
        const bool more = (it + 1 < nIter);
        if (more) {
            int k2o = (it + 1) * 8;
            int nbuf = buf ^ 1;
            const uint32_t* gah = Ah + (size_t)(bm + aRow) * K2 + k2o + aQ;
            const uint32_t* gal = Al + (size_t)(bm + aRow) * K2 + k2o + aQ;
            uint32_t sa = (nbuf*HATILE2 + aRow*HASTR2 + aQ) * 4;
            CP_ASYNC16(ah_u + sa, gah);
            CP_ASYNC16(al_u + sa, gal);
            const uint32_t* gb = (bSel ? Bl : Bh) + (size_t)(k2o + bRow) * N + bn + bQ;
            uint32_t sb = (bSel ? bl_u : bh_u) + (nbuf*HBTILE + bRow*HBSTR + bQ) * 4;
            CP_ASYNC16(sb, gb);
            CP_COMMIT();
            CP_WAIT1();
        } else {
            CP_WAIT0();
        }
        __syncthreads();

        const uint32_t* ahs = Ahs + buf*HATILE2;
        const uint32_t* als = Als + buf*HATILE2;
        const uint32_t* bhs = Bhs + buf*HBTILE;
        const uint32_t* bls = Bls + buf*HBTILE;

        uint32_t ah[2][4], al[2][4];
#pragma unroll
        for (int mf = 0; mf < 2; mf++) {
            const int m = warpM * 32 + mf * 16 + g;
            ah[mf][0] = ahs[m*HASTR2 + tq];
            ah[mf][1] = ahs[(m+8)*HASTR2 + tq];
            ah[mf][2] = ahs[m*HASTR2 + tq + 4];
            ah[mf][3] = ahs[(m+8)*HASTR2 + tq + 4];
            al[mf][0] = als[m*HASTR2 + tq];
            al[mf][1] = als[(m+8)*HASTR2 + tq];
            al[mf][2] = als[m*HASTR2 + tq + 4];
            al[mf][3] = als[(m+8)*HASTR2 + tq + 4];
        }
        uint32_t bh[4][2], bl[4][2];
#pragma unroll
        for (int nf = 0; nf < 4; nf++) {
            const int n = warpN * 32 + nf * 8 + g;
            bh[nf][0] = bhs[tq*HBSTR + n];
            bh[nf][1] = bhs[(tq+4)*HBSTR + n];
            bl[nf][0] = bls[tq*HBSTR + n];
            bl[nf][1] = bls[(tq+4)*HBSTR + n];
        }
#pragma unroll
        for (int mf = 0; mf < 2; mf++)
#pragma unroll
            for (int nf = 0; nf < 4; nf++) mma_bf16(acc[mf][nf], ah[mf], bh[nf]);
#pragma unroll
        for (int mf = 0; mf < 2; mf++)
#pragma unroll
            for (int nf = 0; nf < 4; nf++) mma_bf16(acc[mf][nf], al[mf], bh[nf]);
#pragma unroll
        for (int mf = 0; mf < 2; mf++)
#pragma unroll
            for (int nf = 0; nf < 4; nf++) mma_bf16(acc[mf][nf], ah[mf], bl[nf]);

        __syncthreads();
    }

#pragma unroll
    for (int mf = 0; mf < 2; mf++) {
#pragma unroll
        for (int nf = 0; nf < 4; nf++) {
            const int r0 = bm + warpM * 32 + mf * 16 + g;
            const int c0 = bn + warpN * 32 + nf * 8 + tq * 2;
            float2 bv = *reinterpret_cast<const float2*>(bias + c0);
            float2 o0 = make_float2(acc[mf][nf][0] + bv.x, acc[mf][nf][1] + bv.y);
            float2 o1 = make_float2(acc[mf][nf][2] + bv.x, acc[mf][nf][3] + bv.y);
            *reinterpret_cast<float2*>(C + (size_t)r0 * ldc + c0)       = o0;
            *reinterpret_cast<float2*>(C + (size_t)(r0 + 8) * ldc + c0) = o1;
        }
    }
}

// ------------- compressed keys: mean pool over BLK=8 ---------------------
__global__ __launch_bounds__(64) void kcmp_kernel()
{
    int bhm = blockIdx.x;
    int d = threadIdx.x;
    int bh = bhm / NBc, m = bhm % NBc;
    const float* kr = g_k + ((size_t)bh*Nn + m*BLKc) * Dd;
    float s = 0.f;
#pragma unroll
    for (int t = 0; t < BLKc; t++) s += kr[t*Dd + d];
    g_kcmp[(size_t)bhm*Dd + d] = s * (1.f/BLKc);
}

// ------------- kv/z partials ----------------------------------------------
__global__ __launch_bounds__(256) void kv_chunk_kernel()
{
    int bh = blockIdx.x;
    int ch = blockIdx.y;
    int tid = threadIdx.x;
    int e = tid & 63;
    int dg = tid >> 6;
    __shared__ float sh[4][128];
    float acc[16];
#pragma unroll
    for (int j = 0; j < 16; j++) acc[j] = 0.f;
    float zacc = 0.f;
    size_t base = (size_t)bh * Nn * Dd;
    const int lr = tid >> 6;
    const int lc = (tid & 63) * 2;
    for (int i0 = 0; i0 < CHLEN; i0 += 4) {
        __syncthreads();
        {
            int n = ch * CHLEN + i0 + lr;
            float2 val;
            if (lc < 64)
                val = *reinterpret_cast<const float2*>(g_pk + base + (size_t)n*Dd + lc);
            else
                val = *reinterpret_cast<const float2*>(g_v + base + (size_t)n*Dd + (lc - 64));
            sh[lr][lc]   = val.x;
            sh[lr][lc+1] = val.y;
        }
        __syncthreads();
#pragma unroll
        for (int r = 0; r < 4; r++) {
            float ve = sh[r][64 + e];
#pragma unroll
            for (int j = 0; j < 16; j++) acc[j] += sh[r][dg*16 + j] * ve;
            if (tid < 64) zacc += sh[r][tid];
        }
    }
    float* out = g_kvp + ((size_t)ch * BHc + bh) * (Dd*Dd);
#pragma unroll
    for (int j = 0; j < 16; j++) out[(dg*16 + j)*Dd + e] = acc[j];
    if (tid < 64) g_zp[((size_t)ch * BHc + bh) * Dd + tid] = zacc;
}

__global__ __launch_bounds__(256) void kv_reduce_kernel()
{
    int idx = blockIdx.x * 256 + threadIdx.x;
    const int KVN = BHc*Dd*Dd;
    const int ZN  = BHc*Dd;
    if (idx < KVN) {
        float s = 0.f;
#pragma unroll
        for (int c = 0; c < NCHUNK; c++) s += g_kvp[(size_t)c*KVN + idx];
        g_kv[idx] = s;
    } else if (idx < KVN + ZN) {
        int z = idx - KVN;
        float s = 0.f;
#pragma unroll
        for (int c = 0; c < NCHUNK; c++) s += g_zp[(size_t)c*ZN + z];
        g_z[z] = s;
    }
}

// ------------- router + top-7 : smem-transposed kcmp ---------------------
#define KCSTR 132
__global__ __launch_bounds__(256) void router_topk_kernel()
{
    __shared__ float kct[Dd * KCSTR];
    int bh = blockIdx.x >> 4;
    int n0 = (blockIdx.x & 15) * 64;
    int tid = threadIdx.x;
    int warp = tid >> 5, lane = tid & 31;

    const float* kc = g_kcmp + (size_t)bh * NBc * Dd;
#pragma unroll
    for (int i = 0; i < 32; i++) {
        int idx = tid + i * 256;
        int blk = idx >> 6, d = idx & 63;
        kct[d * KCSTR + blk] = kc[idx];
    }
    __syncthreads();

    const float scale = 0.125f;
    const float NEGINF = -__int_as_float(0x7f800000);

    for (int qi = 0; qi < 8; qi++) {
        int n = n0 + warp * 8 + qi;
        const float* qrow = g_q + ((size_t)bh*Nn + n) * Dd;
        float q0 = qrow[lane], q1 = qrow[lane + 32];
        float s0 = 0.f, s1 = 0.f, s2 = 0.f, s3 = 0.f;
#pragma unroll
        for (int d = 0; d < 64; d++) {
            float qd = (d < 32) ? __shfl_sync(~0u, q0, d)
                                : __shfl_sync(~0u, q1, d - 32);
            float4 kv4 = *reinterpret_cast<const float4*>(&kct[d * KCSTR + lane * 4]);
            s0 += qd * kv4.x; s1 += qd * kv4.y;
            s2 += qd * kv4.z; s3 += qd * kv4.w;
        }
        s0 *= scale; s1 *= scale; s2 *= scale; s3 *= scale;

        int qidx = bh * Nn + n;
#pragma unroll
        for (int r = 0; r < TOPKc; r++) {
            float bv = s0; int bj = 0;
            if (s1 > bv) { bv = s1; bj = 1; }
            if (s2 > bv) { bv = s2; bj = 2; }
            if (s3 > bv) { bv = s3; bj = 3; }
            int bm = lane * 4 + bj;
#pragma unroll
            for (int o = 16; o; o >>= 1) {
                float ov = __shfl_xor_sync(~0u, bv, o);
                int   om = __shfl_xor_sync(~0u, bm, o);
                if (ov > bv || (ov == bv && om < bm)) { bv = ov; bm = om; }
            }
            if ((bm >> 2) == lane) {
                int j = bm & 3;
                if      (j == 0) s0 = NEGINF;
                else if (j == 1) s1 = NEGINF;
                else if (j == 2) s2 = NEGINF;
                else             s3 = NEGINF;
            }
            if (lane == 0) g_topk[(size_t)qidx*TOPKc + r] = bm;
        }
    }
}

// ------------- fused sparse softmax attention + linear branch ------------
__global__ __launch_bounds__(256) void attn_kernel()
{
    int bh = blockIdx.x / (Nn/8);
    int b = bh / Hh, h = bh % Hh;
    int n0 = (blockIdx.x % (Nn/8)) * 8;
    int warp = threadIdx.x >> 5;
    int lane = threadIdx.x & 31;
    int n = n0 + warp;
    __shared__ float sq  [8][64];
    __shared__ float spq [8][64];
    __shared__ float sp  [8][64];
    __shared__ float slog[8][64];
    __shared__ int   sblk[8][8];

    size_t qb = ((size_t)bh*Nn + n) * Dd;
    {
        float2 a = *reinterpret_cast<const float2*>(g_q  + qb + lane*2);
        float2 c = *reinterpret_cast<const float2*>(g_pq + qb + lane*2);
        sq [warp][lane*2] = a.x; sq [warp][lane*2+1] = a.y;
        spq[warp][lane*2] = c.x; spq[warp][lane*2+1] = c.y;
    }
    if (lane < TOPKc) sblk[warp][lane] = g_topk[((size_t)bh*Nn + n)*TOPKc + lane];
    __syncwarp();

    const float scale = 0.125f;
    const int NSEL = TOPKc * BLKc;   // 56
    const float NEGINF = -__int_as_float(0x7f800000);
    const float4* sq4 = reinterpret_cast<const float4*>(sq[warp]);
    const size_t kbase = (size_t)bh * Nn * Dd;
    const int seg = lane & 15;
    float4 qv = sq4[seg];

#pragma unroll 4
    for (int i = 0; i < NSEL/2; i++) {
        int s = 2*i + (lane >> 4);
        int tok = sblk[warp][s >> 3] * BLKc + (s & 7);
        float4 kv = __ldg(reinterpret_cast<const float4*>(g_k + kbase + (size_t)tok * Dd) + seg);
        float a = qv.x*kv.x + qv.y*kv.y + qv.z*kv.z + qv.w*kv.w;
#pragma unroll
        for (int o = 8; o; o >>= 1) a += __shfl_xor_sync(~0u, a, o);
        if (seg == 0) slog[warp][s] = a;
    }
    __syncwarp();

    float l0 = slog[warp][lane] * scale;
    float l1 = (lane + 32 < NSEL) ? slog[warp][lane + 32] * scale : NEGINF;
    float mx = fmaxf(l0, l1);
#pragma unroll
    for (int o = 16; o; o >>= 1) mx = fmaxf(mx, __shfl_xor_sync(~0u, mx, o));
    float e0 = __expf(l0 - mx);
    float e1 = (lane + 32 < NSEL) ? __expf(l1 - mx) : 0.f;
    float se = e0 + e1;
#pragma unroll
    for (int o = 16; o; o >>= 1) se += __shfl_xor_sync(~0u, se, o);
    float inv = 1.f / se;
    sp[warp][lane]      = e0 * inv;
    sp[warp][lane + 32] = e1 * inv;
    __syncwarp();

    const int dd = lane * 2;
    float a0 = 0.f, a1 = 0.f;
#pragma unroll 8
    for (int s = 0; s < NSEL; s++) {
        int tok = sblk[warp][s >> 3] * BLKc + (s & 7);
        float2 vv = *reinterpret_cast<const float2*>(g_v + kbase + (size_t)tok * Dd + dd);
        float p = sp[warp][s];
        a0 += p * vv.x;
        a1 += p * vv.y;
    }

    const float* zr = g_z + (size_t)bh * Dd;
    float pq0 = spq[warp][dd], pq1 = spq[warp][dd + 1];
    float t = pq0 * zr[dd] + pq1 * zr[dd + 1];
#pragma unroll
    for (int o = 16; o; o >>= 1) t += __shfl_xor_sync(~0u, t, o);
    float inv_den = 1.f / (t + 1e-6f);
    const float* kvm = g_kv + (size_t)bh * Dd * Dd;
    float n0a = 0.f, n1a = 0.f;
#pragma unroll
    for (int e = 0; e < 64; e++) {
        float pe = spq[warp][e];
        float2 kv2 = *reinterpret_cast<const float2*>(kvm + e*Dd + dd);
        n0a += pe * kv2.x;
        n1a += pe * kv2.y;
    }
    // epilogue: split to bf16 hi/lo planes directly (pair = dims dd, dd+1)
    float o0 = a0 + n0a * inv_den;
    float o1 = a1 + n1a * inv_den;
    uint32_t ph, pl;
    bf16_split2(o0, o1, ph, pl);
    size_t pidx = ((size_t)(b*Nn + n)) * K2c + (h*Dd + dd)/2;
    g_ah[pidx] = ph;
    g_al[pidx] = pl;
}

// ---------------------------------------------------------------------------
extern "C" void kernel_launch(void* const* d_in, const int* in_sizes, int n_in,
                              void* d_out, int out_size)
{
    const float* x      = (const float*)d_in[0];
    const float* w_qkv  = (const float*)d_in[1];
    const float* b_qkv  = (const float*)d_in[2];
    const float* qw     = (const float*)d_in[3];
    const float* qb     = (const float*)d_in[4];
    const float* kw     = (const float*)d_in[5];
    const float* kb     = (const float*)d_in[6];
    const float* w_proj = (const float*)d_in[7];
    const float* b_proj = (const float*)d_in[8];
    float* out = (float*)d_out;

    void *p_ah, *p_al, *p_wph, *p_wpl;
    cudaGetSymbolAddress(&p_ah, g_ah);   cudaGetSymbolAddress(&p_al, g_al);
    cudaGetSymbolAddress(&p_wph, g_wph); cudaGetSymbolAddress(&p_wpl, g_wpl);

    const int M = Bb*Nn;               // 2048

    // 0) bf16 splits in one launch: x, w_qkv v-cols, w_proj
    split_mega_kernel<<<8192, 256>>>(x, w_qkv, w_proj);

    // 1) fused QKV + LN + phi: blocks 0..511 tf32 q,k; 512..767 bf16 v
    qkv_mega_kernel<<<768, 256>>>(x, w_qkv, b_qkv, qw, qb, kw, kb);

    // 2) compressed keys
    kcmp_kernel<<<BHc*NBc, 64>>>();
    // 3) kv / z
    {
        dim3 grid(BHc, NCHUNK);
        kv_chunk_kernel<<<grid, 256>>>();
        int total = BHc*Dd*Dd + BHc*Dd;
        kv_reduce_kernel<<<(total + 255)/256, 256>>>();
    }
    // 4) router + topk
    router_topk_kernel<<<BHc*(Nn/64), 256>>>();
    // 5) sparse + linear attention (writes bf16 planes for proj)
    attn_kernel<<<BHc*(Nn/8), 256>>>();
    // 6) proj GEMM (3xbf16) directly from attn's planes
    {
        dim3 grid(Cc/GBN, M/GBM);
        gemm_bf16_pre_kernel<<<grid, 256>>>((const uint32_t*)p_ah, (const uint32_t*)p_al,
                                            (const uint32_t*)p_wph, (const uint32_t*)p_wpl,
                                            b_proj, out, K2c, Cc, Cc);
    }
    (void)in_sizes; (void)n_in; (void)out_size;
}